// round 11
// baseline (speedup 1.0000x reference)
#include <cuda_runtime.h>
#include <cstdint>

// ============================================================================
// Fused int8 fake-quant conv3x3(5->10) + conv3x3(10->10), pow2 scales.
// Bit-exact integer arithmetic. R11: conv2 = 3 k-step IMMA for oc0-7 ONLY;
// oc8/9 computed by dp4a on the ALREADY-LOADED A fragment registers (each
// quad collectively holds all 24 k-words) + quad butterfly reduction.
// Epilogue stages removed: direct masked STG.32 (32B sectors per (row,oc)).
// ============================================================================

#define RSY 440   // ys3 row stride bytes (36 px * 12B, padded)

__device__ float g_consts[4];       // inv_s_in, m1, m2, s_o2
__device__ int   g_b1i[10];
__device__ int   g_b2i16[16];       // conv2 bias, padded with zeros
__device__ unsigned g_w1a[90];      // [oc*9+tap]: ch0-3 packed
__device__ unsigned g_w1b[30];      // [oc*3+ky]:  [w4_kx0,w4_kx1,w4_kx2,0]
__device__ unsigned g_b2t[192];     // IMMA B frags [kr(6)][lane(32)], oc0-7
__device__ unsigned g_w89q[48];     // oc8/9 dp4a words [kr(6)][oc2(2)][quad(4)]

__device__ __forceinline__ int clampq(float v) {
    int q = __float2int_rn(v);
    return max(-128, min(127, q));
}
// round-half-even + saturate to s8 (low byte usable)
__device__ __forceinline__ unsigned q8b(float v) {
    unsigned r;
    asm("cvt.rni.sat.s8.f32 %0, %1;" : "=r"(r) : "f"(v));
    return r;
}

__device__ __forceinline__ void imma16832(int* d,
    unsigned a0, unsigned a1, unsigned a2, unsigned a3,
    unsigned b0, unsigned b1) {
    asm volatile(
        "mma.sync.aligned.m16n8k32.row.col.s32.s8.s8.s32 "
        "{%0,%1,%2,%3}, {%4,%5,%6,%7}, {%8,%9}, {%0,%1,%2,%3};\n"
        : "+r"(d[0]), "+r"(d[1]), "+r"(d[2]), "+r"(d[3])
        : "r"(a0), "r"(a1), "r"(a2), "r"(a3), "r"(b0), "r"(b1));
}

// conv2 weight byte for k-word g (0..23), byte b (0..3), output channel n.
// g<18: full words, tap t=g/2, ch=(g&1)*4+b.
// g 18..20: row-paired ch8/9 word, kx=g-18, bytes=(ch8 ky0, ch9 ky0, ch8 ky1, ch9 ky1)
// g 21..23: ky=2 half word, kx=g-21, bytes=(ch8, ch9, 0, 0)
__device__ __forceinline__ int getW2(const float* w2, float sw2, int n, int g, int b) {
    int ch, ky, kx;
    if (g < 18)      { int t = g >> 1; ky = t / 3; kx = t % 3; ch = (g & 1) * 4 + b; }
    else if (g < 21) { kx = g - 18; ky = b >> 1; ch = 8 + (b & 1); }
    else             { if (b >= 2) return 0; kx = g - 21; ky = 2; ch = 8 + b; }
    return clampq(w2[((n * 10 + ch) * 3 + ky) * 3 + kx] / sw2);
}

__global__ void prep_kernel(const float* __restrict__ w1, const float* __restrict__ b1,
                            const float* __restrict__ w2, const float* __restrict__ b2,
                            const float* __restrict__ s_in, const float* __restrict__ s_w1,
                            const float* __restrict__ s_o1, const float* __restrict__ s_w2,
                            const float* __restrict__ s_o2) {
    const int t = threadIdx.x;
    const float si = s_in[0], sw1 = s_w1[0], so1 = s_o1[0], sw2 = s_w2[0], so2 = s_o2[0];
    if (t == 0) {
        g_consts[0] = 1.0f / si;
        g_consts[1] = (si * sw1) / so1;
        g_consts[2] = (so1 * sw2) / so2;
        g_consts[3] = so2;
    }
    if (t < 10) g_b1i[t] = clampq(b1[t] / (si * sw1));
    if (t < 16) g_b2i16[t] = (t < 10) ? clampq(b2[t] / (so1 * sw2)) : 0;
    if (t < 90) {
        const int oc = t / 9, tap = t % 9;
        const int ky = tap / 3, kx = tap % 3;
        unsigned a = 0;
        #pragma unroll
        for (int c = 0; c < 4; c++) {
            int q = clampq(w1[((oc * 5 + c) * 3 + ky) * 3 + kx] / sw1);
            a |= ((unsigned)(q & 0xFF)) << (8 * c);
        }
        g_w1a[t] = a;
    }
    if (t < 30) {
        const int oc = t / 3, ky = t % 3;
        unsigned b = 0;
        #pragma unroll
        for (int kx = 0; kx < 3; kx++) {
            int q = clampq(w1[((oc * 5 + 4) * 3 + ky) * 3 + kx] / sw1);
            b |= ((unsigned)(q & 0xFF)) << (8 * kx);
        }
        g_w1b[t] = b;
    }
    // IMMA B-fragment table (oc0-7): reg kr = s*2+j, word g = s*8 + j*4 + (lane&3)
    for (int idx = t; idx < 192; idx += blockDim.x) {
        const int kr = idx >> 5, lane = idx & 31;
        const int s = kr >> 1, j = kr & 1;
        const int np = lane >> 2;
        const int g = s * 8 + j * 4 + (lane & 3);
        unsigned v = 0;
        #pragma unroll
        for (int b = 0; b < 4; b++)
            v |= ((unsigned)(getW2(w2, sw2, np, g, b) & 0xFF)) << (8 * b);
        g_b2t[idx] = v;
    }
    // oc8/9 dp4a weight words: [kr(6)][oc2(2)][quad(4)], word g = (kr>>1)*8+(kr&1)*4+quad
    for (int idx = t; idx < 48; idx += blockDim.x) {
        const int kr = idx >> 3, oc2 = (idx >> 2) & 1, quad = idx & 3;
        const int g = (kr >> 1) * 8 + (kr & 1) * 4 + quad;
        unsigned v = 0;
        #pragma unroll
        for (int b = 0; b < 4; b++)
            v |= ((unsigned)(getW2(w2, sw2, 8 + oc2, g, b) & 0xFF)) << (8 * b);
        g_w89q[idx] = v;
    }
}

__global__ __launch_bounds__(256, 2)
void fused_conv_kernel(const float* __restrict__ x, float* __restrict__ out) {
    __shared__ __align__(16) unsigned xs4[36][40];        // x ch0-3; 160B rows
    __shared__ __align__(16) unsigned xs1w[36][10];       // x ch4 byte plane
    __shared__ __align__(16) unsigned char ys3[34 * RSY]; // y: 12B/px
    __shared__ unsigned w1a[90], w1b[30];
    __shared__ unsigned b2t[192];
    __shared__ unsigned w89s[48];
    __shared__ int b1s[10];
    __shared__ int b2s16[16];
    __shared__ float cs[4];

    const int tid = threadIdx.x;
    const int n  = blockIdx.z;
    const int ty = blockIdx.y * 32;
    const int tx = blockIdx.x * 32;

    if (tid < 90) w1a[tid] = g_w1a[tid];
    if (tid < 30) w1b[tid] = g_w1b[tid];
    if (tid < 10) b1s[tid] = g_b1i[tid];
    if (tid < 16) b2s16[tid] = g_b2i16[tid];
    if (tid < 4)  cs[tid]  = g_consts[tid];
    if (tid < 192) b2t[tid] = g_b2t[tid];
    if (tid >= 192 && tid < 240) w89s[tid - 192] = g_w89q[tid - 192];
    if (tid >= 96  && tid < 132) { xs1w[tid - 96][9] = 0u; }
    if (tid >= 132 && tid < 204) { int k = tid - 132; xs4[k >> 1][36 + (k & 1)] = 0u; }
    __syncthreads();
    const float inv_s_in = cs[0], m1 = cs[1], m2 = cs[2], so2 = cs[3];

    // ---- Phase A: load + quantize x tile (36 rows x 36 cols, 5 ch) ----
    const float* xb = x + (size_t)n * 1310720u;
    #pragma unroll
    for (int it = 0; it < 2; it++) {
        const int s = tid + it * 256;
        if (s < 324) {
            const int r = s / 9, c4 = s % 9, c = c4 * 4;
            const int gy = ty + r, gx = tx + c;
            float4 v0, v1, v2, v3, v4;
            if (gy < 512 && gx < 512) {
                const float* px = xb + (size_t)gy * 512 + gx;
                v0 = *(const float4*)px;
                v1 = *(const float4*)(px + 262144);
                v2 = *(const float4*)(px + 524288);
                v3 = *(const float4*)(px + 786432);
                v4 = *(const float4*)(px + 1048576);
            } else {
                v0 = v1 = v2 = v3 = v4 = make_float4(0.f, 0.f, 0.f, 0.f);
            }
            uint4 w;
            w.x = __byte_perm(__byte_perm(q8b(v0.x * inv_s_in), q8b(v1.x * inv_s_in), 0x0040),
                              __byte_perm(q8b(v2.x * inv_s_in), q8b(v3.x * inv_s_in), 0x0040), 0x5410);
            w.y = __byte_perm(__byte_perm(q8b(v0.y * inv_s_in), q8b(v1.y * inv_s_in), 0x0040),
                              __byte_perm(q8b(v2.y * inv_s_in), q8b(v3.y * inv_s_in), 0x0040), 0x5410);
            w.z = __byte_perm(__byte_perm(q8b(v0.z * inv_s_in), q8b(v1.z * inv_s_in), 0x0040),
                              __byte_perm(q8b(v2.z * inv_s_in), q8b(v3.z * inv_s_in), 0x0040), 0x5410);
            w.w = __byte_perm(__byte_perm(q8b(v0.w * inv_s_in), q8b(v1.w * inv_s_in), 0x0040),
                              __byte_perm(q8b(v2.w * inv_s_in), q8b(v3.w * inv_s_in), 0x0040), 0x5410);
            *(uint4*)&xs4[r][c] = w;
            xs1w[r][c4] = __byte_perm(__byte_perm(q8b(v4.x * inv_s_in), q8b(v4.y * inv_s_in), 0x0040),
                                      __byte_perm(q8b(v4.z * inv_s_in), q8b(v4.w * inv_s_in), 0x0040), 0x5410);
        }
    }
    __syncthreads();

    // ---- Phase B: conv1 (5->10) dp4a, 6-px strips, 204 tasks ----
    if (tid < 204) {
        const int r = tid / 6, wi = tid % 6, cb = wi * 6;
        unsigned xv[3][8];
        #pragma unroll
        for (int ky = 0; ky < 3; ky++) {
            const uint2* rp = (const uint2*)&xs4[r + ky][cb];
            #pragma unroll
            for (int j = 0; j < 4; j++) {
                const uint2 t = rp[j];
                xv[ky][2 * j] = t.x; xv[ky][2 * j + 1] = t.y;
            }
        }
        unsigned win[3][6];
        const int wbase = cb >> 2;
        #pragma unroll
        for (int ky = 0; ky < 3; ky++) {
            const unsigned A = xs1w[r + ky][wbase];
            const unsigned B = xs1w[r + ky][wbase + 1];
            const unsigned C = xs1w[r + ky][wbase + 2];
            if ((cb & 3) == 0) {
                win[ky][0] = A;
                win[ky][1] = __funnelshift_r(A, B, 8);
                win[ky][2] = __funnelshift_r(A, B, 16);
                win[ky][3] = __funnelshift_r(A, B, 24);
                win[ky][4] = B;
                win[ky][5] = __funnelshift_r(B, C, 8);
            } else {
                win[ky][0] = __funnelshift_r(A, B, 16);
                win[ky][1] = __funnelshift_r(A, B, 24);
                win[ky][2] = B;
                win[ky][3] = __funnelshift_r(B, C, 8);
                win[ky][4] = __funnelshift_r(B, C, 16);
                win[ky][5] = __funnelshift_r(B, C, 24);
            }
        }
        unsigned o0[6], o1[6], q8v[6];
        unsigned short hv[6];
        #pragma unroll
        for (int oc = 0; oc < 10; oc++) {
            int acc[6];
            const int bb = b1s[oc];
            #pragma unroll
            for (int i = 0; i < 6; i++) acc[i] = bb;
            #pragma unroll
            for (int ky = 0; ky < 3; ky++) {
                #pragma unroll
                for (int kx = 0; kx < 3; kx++) {
                    const int w = (int)w1a[oc * 9 + ky * 3 + kx];
                    #pragma unroll
                    for (int i = 0; i < 6; i++)
                        acc[i] = __dp4a((int)xv[ky][i + kx], w, acc[i]);
                }
                const int wb = (int)w1b[oc * 3 + ky];
                #pragma unroll
                for (int i = 0; i < 6; i++)
                    acc[i] = __dp4a((int)win[ky][i], wb, acc[i]);
            }
            #pragma unroll
            for (int i = 0; i < 6; i++) {
                const unsigned q = q8b((float)acc[i] * m1);
                if (oc == 0)      o0[i] = q;
                else if (oc == 1) o0[i] = __byte_perm(o0[i], q, 0x3240);
                else if (oc == 2) o0[i] = __byte_perm(o0[i], q, 0x3410);
                else if (oc == 3) o0[i] = __byte_perm(o0[i], q, 0x4210);
                else if (oc == 4) o1[i] = q;
                else if (oc == 5) o1[i] = __byte_perm(o1[i], q, 0x3240);
                else if (oc == 6) o1[i] = __byte_perm(o1[i], q, 0x3410);
                else if (oc == 7) o1[i] = __byte_perm(o1[i], q, 0x4210);
                else if (oc == 8) q8v[i] = q;
                else hv[i] = (unsigned short)((q8v[i] & 0xFFu) | ((q & 0xFFu) << 8));
            }
        }
        #pragma unroll
        for (int i = 0; i < 6; i++) {
            unsigned char* bp = &ys3[r * RSY + (cb + i) * 12];
            *(unsigned*)(bp)     = o0[i];
            *(unsigned*)(bp + 4) = o1[i];
            *(unsigned short*)(bp + 8) = hv[i];               // own row, low half
            if (r > 0)
                *(unsigned short*)(bp - RSY + 10) = hv[i];    // prev row, high half
        }
    }
    __syncthreads();

    // ---- Phase C: conv2: IMMA (oc0-7) + reg-dp4a+butterfly (oc8/9) ----
    {
        const int lane = tid & 31, warp = tid >> 5;
        const int quad = lane & 3, pxl = lane >> 2;

        unsigned B2r[6];
        #pragma unroll
        for (int kr = 0; kr < 6; kr++) B2r[kr] = b2t[kr * 32 + lane];
        unsigned W8[6], W9[6];
        #pragma unroll
        for (int kr = 0; kr < 6; kr++) {
            W8[kr] = w89s[kr * 8 + quad];
            W9[kr] = w89s[kr * 8 + 4 + quad];
        }
        const int bA0 = b2s16[quad * 2], bA1 = b2s16[quad * 2 + 1];
        const int b89 = b2s16[8 + (quad & 1)];

        // per-thread A k-word offsets for the 3 steps
        int P2[6];
        #pragma unroll
        for (int i = 0; i < 6; i++) {
            const int g = (i >> 1) * 8 + (i & 1) * 4 + quad;
            int off;
            if (g < 18)      { const int t = g >> 1; off = (t / 3) * RSY + (t % 3) * 12 + (g & 1) * 4; }
            else if (g < 21) off = (g - 18) * 12 + 8;
            else             off = 2 * RSY + (g - 21) * 12 + 8;
            P2[i] = off;
        }

        const int px12 = pxl * 12;
        float* ob = out + (size_t)n * 2580640u;
        const int gx = tx + pxl;   // column within tile handled below via cb

        #pragma unroll
        for (int k8 = 0; k8 < 8; k8++) {
            const int mt = k8 * 8 + warp;          // 64 m-tiles (16 row-pairs x 4)
            const int rp = mt >> 2, cb = (mt & 3) * 8;
            const unsigned char* Ab = ys3 + rp * (2 * RSY) + cb * 12 + px12;
            int d0[4] = {bA0, bA1, bA0, bA1};
            int p8r0 = 0, p9r0 = 0, p8r1 = 0, p9r1 = 0;
            #pragma unroll
            for (int s = 0; s < 3; s++) {
                const int a0 = *(const int*)(Ab + P2[2 * s]);
                const int a1 = *(const int*)(Ab + P2[2 * s] + RSY);
                const int a2 = *(const int*)(Ab + P2[2 * s + 1]);
                const int a3 = *(const int*)(Ab + P2[2 * s + 1] + RSY);
                imma16832(d0, (unsigned)a0, (unsigned)a1, (unsigned)a2, (unsigned)a3,
                          B2r[s * 2], B2r[s * 2 + 1]);
                p8r0 = __dp4a(a0, (int)W8[2 * s], p8r0);
                p8r0 = __dp4a(a2, (int)W8[2 * s + 1], p8r0);
                p8r1 = __dp4a(a1, (int)W8[2 * s], p8r1);
                p8r1 = __dp4a(a3, (int)W8[2 * s + 1], p8r1);
                p9r0 = __dp4a(a0, (int)W9[2 * s], p9r0);
                p9r0 = __dp4a(a2, (int)W9[2 * s + 1], p9r0);
                p9r1 = __dp4a(a1, (int)W9[2 * s], p9r1);
                p9r1 = __dp4a(a3, (int)W9[2 * s + 1], p9r1);
            }
            // quad butterfly: reduce partials across the 4 lanes of each quad-group
            p8r0 += __shfl_xor_sync(0xffffffffu, p8r0, 1);
            p8r0 += __shfl_xor_sync(0xffffffffu, p8r0, 2);
            p9r0 += __shfl_xor_sync(0xffffffffu, p9r0, 1);
            p9r0 += __shfl_xor_sync(0xffffffffu, p9r0, 2);
            p8r1 += __shfl_xor_sync(0xffffffffu, p8r1, 1);
            p8r1 += __shfl_xor_sync(0xffffffffu, p8r1, 2);
            p9r1 += __shfl_xor_sync(0xffffffffu, p9r1, 1);
            p9r1 += __shfl_xor_sync(0xffffffffu, p9r1, 2);

            const int gy0 = ty + rp * 2;
            const int gxc = tx + cb + pxl;
            const bool gxok = (gxc < 508);
            float* pb = ob + (size_t)gy0 * 508u + gxc;
            // d0 stores: (row, oc=quad*2+(e&1))
            #pragma unroll
            for (int e = 0; e < 4; e++) {
                const int row = e >> 1, oc = quad * 2 + (e & 1);
                const float f = fminf(fmaxf(rintf((float)d0[e] * m2), -128.f), 127.f) * so2;
                if (gxok && (gy0 + row) < 508)
                    pb[(size_t)oc * 258064u + (size_t)row * 508u] = f;
            }
            // oc8/9 store: thread's assigned value by quad
            {
                const int row = quad >> 1, oc = 8 + (quad & 1);
                const int v = (quad == 0) ? p8r0 : (quad == 1) ? p9r0
                            : (quad == 2) ? p8r1 : p9r1;
                const float f = fminf(fmaxf(rintf((float)(v + b89) * m2), -128.f), 127.f) * so2;
                if (gxok && (gy0 + row) < 508)
                    pb[(size_t)oc * 258064u + (size_t)row * 508u] = f;
            }
        }
        (void)gx;
    }
}

extern "C" void kernel_launch(void* const* d_in, const int* in_sizes, int n_in,
                              void* d_out, int out_size) {
    const float* x    = (const float*)d_in[0];
    const float* w1   = (const float*)d_in[1];
    const float* b1   = (const float*)d_in[2];
    const float* w2   = (const float*)d_in[3];
    const float* b2   = (const float*)d_in[4];
    const float* s_in = (const float*)d_in[5];
    const float* s_w1 = (const float*)d_in[6];
    const float* s_o1 = (const float*)d_in[7];
    const float* s_w2 = (const float*)d_in[8];
    const float* s_o2 = (const float*)d_in[9];

    prep_kernel<<<1, 256>>>(w1, b1, w2, b2, s_in, s_w1, s_o1, s_w2, s_o2);

    dim3 grid(16, 16, 32);   // 32x32 tiles over 508x508, batch 32
    fused_conv_kernel<<<grid, 256>>>(x, (float*)d_out);
}

// round 12
// speedup vs baseline: 1.2725x; 1.2725x over previous
#include <cuda_runtime.h>
#include <cstdint>

// ============================================================================
// Fused int8 fake-quant conv3x3(5->10) + conv3x3(10->10), pow2 scales.
// Bit-exact integer arithmetic. R12 = R11 (IMMA oc0-7 + reg-reuse dp4a oc8/9)
// with occupancy restored: launch_bounds(256,3) (R11's 111 regs -> 24% occ was
// the regression cause) and the quad reduction cut from 8 shfl to a 3-shfl
// reduce-scatter butterfly.
// ============================================================================

#define RSY 440   // ys3 row stride bytes (36 px * 12B, padded)

__device__ float g_consts[4];       // inv_s_in, m1, m2, s_o2
__device__ int   g_b1i[10];
__device__ int   g_b2i16[16];       // conv2 bias, padded with zeros
__device__ unsigned g_w1a[90];      // [oc*9+tap]: ch0-3 packed
__device__ unsigned g_w1b[30];      // [oc*3+ky]:  [w4_kx0,w4_kx1,w4_kx2,0]
__device__ unsigned g_b2t[192];     // IMMA B frags [kr(6)][lane(32)], oc0-7
__device__ unsigned g_w89q[48];     // oc8/9 dp4a words [kr(6)][oc2(2)][quad(4)]

__device__ __forceinline__ int clampq(float v) {
    int q = __float2int_rn(v);
    return max(-128, min(127, q));
}
// round-half-even + saturate to s8 (low byte usable)
__device__ __forceinline__ unsigned q8b(float v) {
    unsigned r;
    asm("cvt.rni.sat.s8.f32 %0, %1;" : "=r"(r) : "f"(v));
    return r;
}

__device__ __forceinline__ void imma16832(int* d,
    unsigned a0, unsigned a1, unsigned a2, unsigned a3,
    unsigned b0, unsigned b1) {
    asm volatile(
        "mma.sync.aligned.m16n8k32.row.col.s32.s8.s8.s32 "
        "{%0,%1,%2,%3}, {%4,%5,%6,%7}, {%8,%9}, {%0,%1,%2,%3};\n"
        : "+r"(d[0]), "+r"(d[1]), "+r"(d[2]), "+r"(d[3])
        : "r"(a0), "r"(a1), "r"(a2), "r"(a3), "r"(b0), "r"(b1));
}

// conv2 weight byte for k-word g (0..23), byte b (0..3), output channel n.
__device__ __forceinline__ int getW2(const float* w2, float sw2, int n, int g, int b) {
    int ch, ky, kx;
    if (g < 18)      { int t = g >> 1; ky = t / 3; kx = t % 3; ch = (g & 1) * 4 + b; }
    else if (g < 21) { kx = g - 18; ky = b >> 1; ch = 8 + (b & 1); }
    else             { if (b >= 2) return 0; kx = g - 21; ky = 2; ch = 8 + b; }
    return clampq(w2[((n * 10 + ch) * 3 + ky) * 3 + kx] / sw2);
}

__global__ void prep_kernel(const float* __restrict__ w1, const float* __restrict__ b1,
                            const float* __restrict__ w2, const float* __restrict__ b2,
                            const float* __restrict__ s_in, const float* __restrict__ s_w1,
                            const float* __restrict__ s_o1, const float* __restrict__ s_w2,
                            const float* __restrict__ s_o2) {
    const int t = threadIdx.x;
    const float si = s_in[0], sw1 = s_w1[0], so1 = s_o1[0], sw2 = s_w2[0], so2 = s_o2[0];
    if (t == 0) {
        g_consts[0] = 1.0f / si;
        g_consts[1] = (si * sw1) / so1;
        g_consts[2] = (so1 * sw2) / so2;
        g_consts[3] = so2;
    }
    if (t < 10) g_b1i[t] = clampq(b1[t] / (si * sw1));
    if (t < 16) g_b2i16[t] = (t < 10) ? clampq(b2[t] / (so1 * sw2)) : 0;
    if (t < 90) {
        const int oc = t / 9, tap = t % 9;
        const int ky = tap / 3, kx = tap % 3;
        unsigned a = 0;
        #pragma unroll
        for (int c = 0; c < 4; c++) {
            int q = clampq(w1[((oc * 5 + c) * 3 + ky) * 3 + kx] / sw1);
            a |= ((unsigned)(q & 0xFF)) << (8 * c);
        }
        g_w1a[t] = a;
    }
    if (t < 30) {
        const int oc = t / 3, ky = t % 3;
        unsigned b = 0;
        #pragma unroll
        for (int kx = 0; kx < 3; kx++) {
            int q = clampq(w1[((oc * 5 + 4) * 3 + ky) * 3 + kx] / sw1);
            b |= ((unsigned)(q & 0xFF)) << (8 * kx);
        }
        g_w1b[t] = b;
    }
    // IMMA B-fragment table (oc0-7): reg kr = s*2+j, word g = s*8 + j*4 + (lane&3)
    for (int idx = t; idx < 192; idx += blockDim.x) {
        const int kr = idx >> 5, lane = idx & 31;
        const int s = kr >> 1, j = kr & 1;
        const int np = lane >> 2;
        const int g = s * 8 + j * 4 + (lane & 3);
        unsigned v = 0;
        #pragma unroll
        for (int b = 0; b < 4; b++)
            v |= ((unsigned)(getW2(w2, sw2, np, g, b) & 0xFF)) << (8 * b);
        g_b2t[idx] = v;
    }
    // oc8/9 dp4a weight words: [kr(6)][oc2(2)][quad(4)], word g = (kr>>1)*8+(kr&1)*4+quad
    for (int idx = t; idx < 48; idx += blockDim.x) {
        const int kr = idx >> 3, oc2 = (idx >> 2) & 1, quad = idx & 3;
        const int g = (kr >> 1) * 8 + (kr & 1) * 4 + quad;
        unsigned v = 0;
        #pragma unroll
        for (int b = 0; b < 4; b++)
            v |= ((unsigned)(getW2(w2, sw2, 8 + oc2, g, b) & 0xFF)) << (8 * b);
        g_w89q[idx] = v;
    }
}

__global__ __launch_bounds__(256, 3)
void fused_conv_kernel(const float* __restrict__ x, float* __restrict__ out) {
    __shared__ __align__(16) unsigned xs4[36][40];        // x ch0-3; 160B rows
    __shared__ __align__(16) unsigned xs1w[36][10];       // x ch4 byte plane
    __shared__ __align__(16) unsigned char ys3[34 * RSY]; // y: 12B/px
    __shared__ unsigned w1a[90], w1b[30];
    __shared__ unsigned b2t[192];
    __shared__ unsigned w89s[48];
    __shared__ int b1s[10];
    __shared__ int b2s16[16];
    __shared__ float cs[4];

    const int tid = threadIdx.x;
    const int n  = blockIdx.z;
    const int ty = blockIdx.y * 32;
    const int tx = blockIdx.x * 32;

    if (tid < 90) w1a[tid] = g_w1a[tid];
    if (tid < 30) w1b[tid] = g_w1b[tid];
    if (tid < 10) b1s[tid] = g_b1i[tid];
    if (tid < 16) b2s16[tid] = g_b2i16[tid];
    if (tid < 4)  cs[tid]  = g_consts[tid];
    if (tid < 192) b2t[tid] = g_b2t[tid];
    if (tid >= 192 && tid < 240) w89s[tid - 192] = g_w89q[tid - 192];
    if (tid >= 96  && tid < 132) { xs1w[tid - 96][9] = 0u; }
    if (tid >= 132 && tid < 204) { int k = tid - 132; xs4[k >> 1][36 + (k & 1)] = 0u; }
    __syncthreads();
    const float inv_s_in = cs[0], m1 = cs[1], m2 = cs[2], so2 = cs[3];

    // ---- Phase A: load + quantize x tile (36 rows x 36 cols, 5 ch) ----
    const float* xb = x + (size_t)n * 1310720u;
    #pragma unroll
    for (int it = 0; it < 2; it++) {
        const int s = tid + it * 256;
        if (s < 324) {
            const int r = s / 9, c4 = s % 9, c = c4 * 4;
            const int gy = ty + r, gx = tx + c;
            float4 v0, v1, v2, v3, v4;
            if (gy < 512 && gx < 512) {
                const float* px = xb + (size_t)gy * 512 + gx;
                v0 = *(const float4*)px;
                v1 = *(const float4*)(px + 262144);
                v2 = *(const float4*)(px + 524288);
                v3 = *(const float4*)(px + 786432);
                v4 = *(const float4*)(px + 1048576);
            } else {
                v0 = v1 = v2 = v3 = v4 = make_float4(0.f, 0.f, 0.f, 0.f);
            }
            uint4 w;
            w.x = __byte_perm(__byte_perm(q8b(v0.x * inv_s_in), q8b(v1.x * inv_s_in), 0x0040),
                              __byte_perm(q8b(v2.x * inv_s_in), q8b(v3.x * inv_s_in), 0x0040), 0x5410);
            w.y = __byte_perm(__byte_perm(q8b(v0.y * inv_s_in), q8b(v1.y * inv_s_in), 0x0040),
                              __byte_perm(q8b(v2.y * inv_s_in), q8b(v3.y * inv_s_in), 0x0040), 0x5410);
            w.z = __byte_perm(__byte_perm(q8b(v0.z * inv_s_in), q8b(v1.z * inv_s_in), 0x0040),
                              __byte_perm(q8b(v2.z * inv_s_in), q8b(v3.z * inv_s_in), 0x0040), 0x5410);
            w.w = __byte_perm(__byte_perm(q8b(v0.w * inv_s_in), q8b(v1.w * inv_s_in), 0x0040),
                              __byte_perm(q8b(v2.w * inv_s_in), q8b(v3.w * inv_s_in), 0x0040), 0x5410);
            *(uint4*)&xs4[r][c] = w;
            xs1w[r][c4] = __byte_perm(__byte_perm(q8b(v4.x * inv_s_in), q8b(v4.y * inv_s_in), 0x0040),
                                      __byte_perm(q8b(v4.z * inv_s_in), q8b(v4.w * inv_s_in), 0x0040), 0x5410);
        }
    }
    __syncthreads();

    // ---- Phase B: conv1 (5->10) dp4a, 6-px strips, 204 tasks ----
    if (tid < 204) {
        const int r = tid / 6, wi = tid % 6, cb = wi * 6;
        unsigned xv[3][8];
        #pragma unroll
        for (int ky = 0; ky < 3; ky++) {
            const uint2* rp = (const uint2*)&xs4[r + ky][cb];
            #pragma unroll
            for (int j = 0; j < 4; j++) {
                const uint2 t = rp[j];
                xv[ky][2 * j] = t.x; xv[ky][2 * j + 1] = t.y;
            }
        }
        unsigned win[3][6];
        const int wbase = cb >> 2;
        #pragma unroll
        for (int ky = 0; ky < 3; ky++) {
            const unsigned A = xs1w[r + ky][wbase];
            const unsigned B = xs1w[r + ky][wbase + 1];
            const unsigned C = xs1w[r + ky][wbase + 2];
            if ((cb & 3) == 0) {
                win[ky][0] = A;
                win[ky][1] = __funnelshift_r(A, B, 8);
                win[ky][2] = __funnelshift_r(A, B, 16);
                win[ky][3] = __funnelshift_r(A, B, 24);
                win[ky][4] = B;
                win[ky][5] = __funnelshift_r(B, C, 8);
            } else {
                win[ky][0] = __funnelshift_r(A, B, 16);
                win[ky][1] = __funnelshift_r(A, B, 24);
                win[ky][2] = B;
                win[ky][3] = __funnelshift_r(B, C, 8);
                win[ky][4] = __funnelshift_r(B, C, 16);
                win[ky][5] = __funnelshift_r(B, C, 24);
            }
        }
        unsigned o0[6], o1[6], q8v[6];
        unsigned short hv[6];
        #pragma unroll
        for (int oc = 0; oc < 10; oc++) {
            int acc[6];
            const int bb = b1s[oc];
            #pragma unroll
            for (int i = 0; i < 6; i++) acc[i] = bb;
            #pragma unroll
            for (int ky = 0; ky < 3; ky++) {
                #pragma unroll
                for (int kx = 0; kx < 3; kx++) {
                    const int w = (int)w1a[oc * 9 + ky * 3 + kx];
                    #pragma unroll
                    for (int i = 0; i < 6; i++)
                        acc[i] = __dp4a((int)xv[ky][i + kx], w, acc[i]);
                }
                const int wb = (int)w1b[oc * 3 + ky];
                #pragma unroll
                for (int i = 0; i < 6; i++)
                    acc[i] = __dp4a((int)win[ky][i], wb, acc[i]);
            }
            #pragma unroll
            for (int i = 0; i < 6; i++) {
                const unsigned q = q8b((float)acc[i] * m1);
                if (oc == 0)      o0[i] = q;
                else if (oc == 1) o0[i] = __byte_perm(o0[i], q, 0x3240);
                else if (oc == 2) o0[i] = __byte_perm(o0[i], q, 0x3410);
                else if (oc == 3) o0[i] = __byte_perm(o0[i], q, 0x4210);
                else if (oc == 4) o1[i] = q;
                else if (oc == 5) o1[i] = __byte_perm(o1[i], q, 0x3240);
                else if (oc == 6) o1[i] = __byte_perm(o1[i], q, 0x3410);
                else if (oc == 7) o1[i] = __byte_perm(o1[i], q, 0x4210);
                else if (oc == 8) q8v[i] = q;
                else hv[i] = (unsigned short)((q8v[i] & 0xFFu) | ((q & 0xFFu) << 8));
            }
        }
        #pragma unroll
        for (int i = 0; i < 6; i++) {
            unsigned char* bp = &ys3[r * RSY + (cb + i) * 12];
            *(unsigned*)(bp)     = o0[i];
            *(unsigned*)(bp + 4) = o1[i];
            *(unsigned short*)(bp + 8) = hv[i];               // own row, low half
            if (r > 0)
                *(unsigned short*)(bp - RSY + 10) = hv[i];    // prev row, high half
        }
    }
    __syncthreads();

    // ---- Phase C: conv2: IMMA (oc0-7) + reg-dp4a + 3-shfl reduce-scatter (oc8/9) ----
    {
        const int lane = tid & 31, warp = tid >> 5;
        const int quad = lane & 3, pxl = lane >> 2;

        unsigned B2r[6];
        #pragma unroll
        for (int kr = 0; kr < 6; kr++) B2r[kr] = b2t[kr * 32 + lane];
        unsigned W8[6], W9[6];
        #pragma unroll
        for (int kr = 0; kr < 6; kr++) {
            W8[kr] = w89s[kr * 8 + quad];
            W9[kr] = w89s[kr * 8 + 4 + quad];
        }
        const int bA0 = b2s16[quad * 2], bA1 = b2s16[quad * 2 + 1];
        const int b89 = b2s16[8 + (quad & 1)];

        // per-thread A k-word offsets for the 3 steps
        int P2[6];
        #pragma unroll
        for (int i = 0; i < 6; i++) {
            const int g = (i >> 1) * 8 + (i & 1) * 4 + quad;
            int off;
            if (g < 18)      { const int t = g >> 1; off = (t / 3) * RSY + (t % 3) * 12 + (g & 1) * 4; }
            else if (g < 21) off = (g - 18) * 12 + 8;
            else             off = 2 * RSY + (g - 21) * 12 + 8;
            P2[i] = off;
        }

        const int px12 = pxl * 12;
        float* ob = out + (size_t)n * 2580640u;
        const bool q1 = (quad & 1) != 0, q2 = (quad & 2) != 0;

        #pragma unroll
        for (int k8 = 0; k8 < 8; k8++) {
            const int mt = k8 * 8 + warp;          // 64 m-tiles (16 row-pairs x 4)
            const int rp = mt >> 2, cb = (mt & 3) * 8;
            const unsigned char* Ab = ys3 + rp * (2 * RSY) + cb * 12 + px12;
            int d0[4] = {bA0, bA1, bA0, bA1};
            int p8r0 = 0, p9r0 = 0, p8r1 = 0, p9r1 = 0;
            #pragma unroll
            for (int s = 0; s < 3; s++) {
                const int a0 = *(const int*)(Ab + P2[2 * s]);
                const int a1 = *(const int*)(Ab + P2[2 * s] + RSY);
                const int a2 = *(const int*)(Ab + P2[2 * s + 1]);
                const int a3 = *(const int*)(Ab + P2[2 * s + 1] + RSY);
                imma16832(d0, (unsigned)a0, (unsigned)a1, (unsigned)a2, (unsigned)a3,
                          B2r[s * 2], B2r[s * 2 + 1]);
                p8r0 = __dp4a(a0, (int)W8[2 * s], p8r0);
                p8r0 = __dp4a(a2, (int)W8[2 * s + 1], p8r0);
                p8r1 = __dp4a(a1, (int)W8[2 * s], p8r1);
                p8r1 = __dp4a(a3, (int)W8[2 * s + 1], p8r1);
                p9r0 = __dp4a(a0, (int)W9[2 * s], p9r0);
                p9r0 = __dp4a(a2, (int)W9[2 * s + 1], p9r0);
                p9r1 = __dp4a(a1, (int)W9[2 * s], p9r1);
                p9r1 = __dp4a(a3, (int)W9[2 * s + 1], p9r1);
            }
            // 3-shfl reduce-scatter across the quad. Targets t: P[0]=p8r0(row0,oc8),
            // P[1]=p9r0(row0,oc9), P[2]=p8r1(row1,oc8), P[3]=p9r1(row1,oc9);
            // lane with quad q ends up owning target t=q.
            const int s0 = q1 ? p8r0 : p9r0;
            const int s1 = q1 ? p8r1 : p9r1;
            const int k0 = (q1 ? p9r0 : p8r0) + __shfl_xor_sync(0xffffffffu, s0, 1);
            const int k1 = (q1 ? p9r1 : p8r1) + __shfl_xor_sync(0xffffffffu, s1, 1);
            const int s2 = q2 ? k0 : k1;
            const int v  = (q2 ? k1 : k0) + __shfl_xor_sync(0xffffffffu, s2, 2);

            const int gy0 = ty + rp * 2;
            const int gxc = tx + cb + pxl;
            const bool gxok = (gxc < 508);
            float* pb = ob + (size_t)gy0 * 508u + gxc;
            // d0 stores: (row = e>>1, oc = quad*2 + (e&1))
            #pragma unroll
            for (int e = 0; e < 4; e++) {
                const int row = e >> 1, oc = quad * 2 + (e & 1);
                const float f = fminf(fmaxf(rintf((float)d0[e] * m2), -128.f), 127.f) * so2;
                if (gxok && (gy0 + row) < 508)
                    pb[(size_t)oc * 258064u + (size_t)row * 508u] = f;
            }
            // oc8/9 store: this thread owns target t = quad
            {
                const int row = quad >> 1, oc = 8 + (quad & 1);
                const float f = fminf(fmaxf(rintf((float)(v + b89) * m2), -128.f), 127.f) * so2;
                if (gxok && (gy0 + row) < 508)
                    pb[(size_t)oc * 258064u + (size_t)row * 508u] = f;
            }
        }
    }
}

extern "C" void kernel_launch(void* const* d_in, const int* in_sizes, int n_in,
                              void* d_out, int out_size) {
    const float* x    = (const float*)d_in[0];
    const float* w1   = (const float*)d_in[1];
    const float* b1   = (const float*)d_in[2];
    const float* w2   = (const float*)d_in[3];
    const float* b2   = (const float*)d_in[4];
    const float* s_in = (const float*)d_in[5];
    const float* s_w1 = (const float*)d_in[6];
    const float* s_o1 = (const float*)d_in[7];
    const float* s_w2 = (const float*)d_in[8];
    const float* s_o2 = (const float*)d_in[9];

    prep_kernel<<<1, 256>>>(w1, b1, w2, b2, s_in, s_w1, s_o1, s_w2, s_o2);

    dim3 grid(16, 16, 32);   // 32x32 tiles over 508x508, batch 32
    fused_conv_kernel<<<grid, 256>>>(x, (float*)d_out);
}